// round 14
// baseline (speedup 1.0000x reference)
#include <cuda_runtime.h>
#include <cuda_fp16.h>
#include <cstdint>

// BinaryConv2d via Winograd F(2x2,3x3) + mma.sync HMMA.
// R14: 2-stage bulk-DMA double buffer, 96 KB/CTA -> 2 CTAs/SM cross-overlap.

#define NB 32
#define CI 128
#define CO 256
#define HH 56
#define HP 58
#define PIXN (HH*HH)
#define TPI  784              // 28*28 tiles per image
#define NTILE (NB*TPI)        // 25088
#define NBLK  196             // NTILE/128
#define XNPER 8
#define NITER (2*XNPER)       // 16 k-chunks per CTA
#define STAGES 2

// padded NHWC fp16
__device__ __half g_xp[(size_t)NB*HP*HP*128];
// Winograd input, chunked+swizzled: [(xn*392 + blk*2 + sub)][pix(128)][64 halfs swz]
__device__ __align__(256) __half g_u2[(size_t)16*NBLK*2*128*64];
// Winograd weights, chunked+swizzled: [(xn*2+sub)][oc(256)][64 halfs swz]
__device__ __align__(256) __half g_v2[(size_t)16*2*256*64];
// GEMM result M[xn][tile][oc]
__device__ __align__(16) __half g_m[(size_t)16*NTILE*CO];

// ---------------- stage 1: pad + fp16 ----------------
__global__ __launch_bounds__(256)
void transform_x_kernel(const float* __restrict__ x) {
    __shared__ float s[128][57];
    const int hp = blockIdx.x % HP;
    const int n  = blockIdx.x / HP;
    const int tid = threadIdx.x;
    const bool interior_h = (hp >= 1 && hp <= HH);

    if (interior_h) {
        const int h = hp - 1;
        const float* src = x + ((size_t)n * CI * HH + h) * HH;
        for (int idx = tid; idx < CI * HH; idx += 256) {
            int c = idx / HH, w = idx - (idx / HH) * HH;
            s[c][w] = src[(size_t)c * PIXN + w];
        }
    }
    __syncthreads();

    const int c  = tid & 127;
    const int wh = tid >> 7;
    __half* ob = g_xp + ((size_t)(n * HP + hp) * HP) * 128 + c;
#pragma unroll 4
    for (int wp = wh * 29; wp < wh * 29 + 29; wp++) {
        float v = 0.0f;
        if (interior_h && wp >= 1 && wp <= HH) v = s[c][wp - 1];
        ob[(size_t)wp * 128] = __float2half_rn(v);
    }
}

// ---------------- stage 2: input Winograd transform (half2, swizzled chunk layout) ----------------
__global__ __launch_bounds__(256)
void winograd_x_kernel() {
    int idx = blockIdx.x * 256 + threadIdx.x;    // over NTILE*64 (channel pairs)
    int c2 = idx & 63;
    int t  = idx >> 6;
    int n  = t / TPI;
    int r  = t - n * TPI;
    int ti = r / 28, tj = r - (r / 28) * 28;

    const __half* base = g_xp + ((size_t)(n * HP + 2 * ti) * HP + 2 * tj) * 128 + 2 * c2;
    float d0[4][4], d1[4][4];
#pragma unroll
    for (int i = 0; i < 4; i++)
#pragma unroll
        for (int s = 0; s < 4; s++) {
            __half2 hv = *(const __half2*)(base + (size_t)(i * HP + s) * 128);
            d0[i][s] = __low2float(hv);
            d1[i][s] = __high2float(hv);
        }

    float t0[4][4], t1[4][4];
#pragma unroll
    for (int s = 0; s < 4; s++) {
        t0[0][s] = d0[0][s] - d0[2][s];  t1[0][s] = d1[0][s] - d1[2][s];
        t0[1][s] = d0[1][s] + d0[2][s];  t1[1][s] = d1[1][s] + d1[2][s];
        t0[2][s] = d0[2][s] - d0[1][s];  t1[2][s] = d1[2][s] - d1[1][s];
        t0[3][s] = d0[1][s] - d0[3][s];  t1[3][s] = d1[1][s] - d1[3][s];
    }
    float u0[4][4], u1[4][4];
#pragma unroll
    for (int i = 0; i < 4; i++) {
        u0[i][0] = t0[i][0] - t0[i][2];  u1[i][0] = t1[i][0] - t1[i][2];
        u0[i][1] = t0[i][1] + t0[i][2];  u1[i][1] = t1[i][1] + t1[i][2];
        u0[i][2] = t0[i][2] - t0[i][1];  u1[i][2] = t1[i][2] - t1[i][1];
        u0[i][3] = t0[i][1] - t0[i][3];  u1[i][3] = t1[i][1] - t1[i][3];
    }

    const int blk = t >> 7;
    const int pix = t & 127;
    const int c   = 2 * c2;
    const int sub = c >> 6;
    const int e   = c & 7;                          // even
    const int uw  = ((c >> 3) & 7) ^ (pix & 7);     // swizzled 16B unit
    const size_t inner = ((size_t)pix * 64) + uw * 8 + e;
#pragma unroll
    for (int xi = 0; xi < 4; xi++)
#pragma unroll
        for (int nu = 0; nu < 4; nu++) {
            int xn = xi * 4 + nu;
            *(__half2*)&g_u2[((size_t)xn * (NBLK * 2) + blk * 2 + sub) * 8192 + inner] =
                __floats2half2_rn(u0[xi][nu], u1[xi][nu]);
        }
}

// ---------------- stage 3: weight Winograd transform (swizzled chunk layout) ----------------
__global__ __launch_bounds__(256)
void winograd_w_kernel(const float* __restrict__ w) {
    int idx = blockIdx.x * 256 + threadIdx.x;    // over CO*CI
    if (idx >= CO * CI) return;
    int oc = idx >> 7;
    int c  = idx & 127;
    float g[3][3];
#pragma unroll
    for (int r = 0; r < 3; r++)
#pragma unroll
        for (int s = 0; s < 3; s++)
            g[r][s] = (w[((size_t)(oc * CI + c)) * 9 + r * 3 + s] >= 0.0f) ? 1.0f : -1.0f;
    float gg[4][3];
#pragma unroll
    for (int s = 0; s < 3; s++) {
        gg[0][s] = g[0][s];
        gg[1][s] = 0.5f * (g[0][s] + g[1][s] + g[2][s]);
        gg[2][s] = 0.5f * (g[0][s] - g[1][s] + g[2][s]);
        gg[3][s] = g[2][s];
    }
    const int sub = c >> 6;
    const int e   = c & 7;
    const int uw  = ((c >> 3) & 7) ^ (oc & 7);
    const size_t inner = ((size_t)oc * 64) + uw * 8 + e;
#pragma unroll
    for (int i = 0; i < 4; i++) {
        float v[4];
        v[0] = gg[i][0];
        v[1] = 0.5f * (gg[i][0] + gg[i][1] + gg[i][2]);
        v[2] = 0.5f * (gg[i][0] - gg[i][1] + gg[i][2]);
        v[3] = gg[i][2];
#pragma unroll
        for (int nu = 0; nu < 4; nu++) {
            int xn = i * 4 + nu;
            g_v2[((size_t)xn * 2 + sub) * 16384 + inner] = __float2half_rn(v[nu]);
        }
    }
}

// ---------------- GEMM kernel ----------------
__device__ __forceinline__ uint32_t smem_u32(const void* p) {
    uint32_t a;
    asm("{ .reg .u64 t; cvta.to.shared.u64 t, %1; cvt.u32.u64 %0, t; }" : "=r"(a) : "l"(p));
    return a;
}
__device__ __forceinline__ void bulk_cp(uint32_t dst, const void* src, uint32_t bytes, uint32_t mbar) {
    asm volatile("cp.async.bulk.shared::cta.global.mbarrier::complete_tx::bytes [%0], [%1], %2, [%3];"
        :: "r"(dst), "l"(src), "r"(bytes), "r"(mbar) : "memory");
}
#define MBAR_INIT(a, c) asm volatile("mbarrier.init.shared.b64 [%0], %1;" :: "r"(a), "r"(c) : "memory")
#define MBAR_EXPECT(a, b) asm volatile("mbarrier.arrive.expect_tx.shared.b64 _, [%0], %1;" :: "r"(a), "r"(b) : "memory")
#define FENCE_ASYNC() asm volatile("fence.proxy.async.shared::cta;" ::: "memory")
#define MBAR_WAIT(a, ph) do { \
    uint32_t _m = (a); uint32_t _p = (ph); uint32_t _d; \
    asm volatile("{\n\t.reg .pred p;\n\tmbarrier.try_wait.parity.acquire.cta.shared::cta.b64 p, [%1], %2;\n\tselp.b32 %0,1,0,p;\n\t}" \
        : "=r"(_d) : "r"(_m), "r"(_p) : "memory"); \
    if (!_d) { \
        asm volatile("{\n\t.reg .pred P1;\nWL_%=:\n\tmbarrier.try_wait.parity.acquire.cta.shared::cta.b64 P1, [%0], %1, 0x989680;\n\t@P1 bra.uni WD_%=;\n\tbra.uni WL_%=;\nWD_%=:\n\t}" \
            :: "r"(_m), "r"(_p) : "memory"); \
    } } while (0)

__device__ __forceinline__ void ldsm4(uint32_t* r, uint32_t addr) {
    asm volatile("ldmatrix.sync.aligned.m8n8.x4.shared.b16 {%0,%1,%2,%3}, [%4];"
        : "=r"(r[0]), "=r"(r[1]), "=r"(r[2]), "=r"(r[3]) : "r"(addr));
}
__device__ __forceinline__ void mma16816(float* c, const uint32_t* a, uint32_t b0, uint32_t b1) {
    asm volatile("mma.sync.aligned.m16n8k16.row.col.f32.f16.f16.f32 "
        "{%0,%1,%2,%3}, {%4,%5,%6,%7}, {%8,%9}, {%0,%1,%2,%3};"
        : "+f"(c[0]), "+f"(c[1]), "+f"(c[2]), "+f"(c[3])
        : "r"(a[0]), "r"(a[1]), "r"(a[2]), "r"(a[3]), "r"(b0), "r"(b1));
}

#define A_ST  16384                  // 128 pix x 64 k x fp16 (swizzled rows)
#define B_ST  32768                  // 256 oc  x 64 k x fp16 (swizzled rows)
#define ST_BYTES (A_ST + B_ST)       // 48 KB / stage
#define SMEM_SZ (STAGES * ST_BYTES)  // 96 KB -> 2 CTAs/SM

__global__ __launch_bounds__(512, 2)
void binconv_wino_gemm(void) {
    extern __shared__ char smem[];
    __shared__ __align__(8) uint64_t mbar[STAGES];
    const uint32_t sb = smem_u32(smem);
    const uint32_t mb = smem_u32(&mbar[0]);

    const int tid  = threadIdx.x;
    const int wid  = tid >> 5;
    const int lane = tid & 31;
    const int blk  = blockIdx.x;
    const int t0   = blk * 128;
    const int xn0  = blockIdx.y * XNPER;

    if (tid == 0) {
#pragma unroll
        for (int s = 0; s < STAGES; s++) MBAR_INIT(mb + s * 8, 1);
    }
    __syncthreads();

    auto issue = [&](int kk) {
        if (kk < NITER) {
            const int s   = kk & 1;
            const int xl  = kk >> 1;
            const int sub = kk & 1;
            const uint32_t soff = (uint32_t)s * ST_BYTES;
            MBAR_EXPECT(mb + s * 8, (uint32_t)ST_BYTES);
            bulk_cp(sb + soff,
                    g_u2 + ((size_t)(xn0 + xl) * (NBLK * 2) + blk * 2 + sub) * 8192,
                    A_ST, mb + s * 8);
            bulk_cp(sb + A_ST + soff,
                    g_v2 + ((size_t)(xn0 + xl) * 2 + sub) * 16384,
                    B_ST, mb + s * 8);
        }
    };

    if (tid == 0) { FENCE_ASYNC(); issue(0); issue(1); }

    // warp tiling: 4 (M) x 4 (N); warp tile 32 x 64
    const int wm = (wid & 3) * 32;
    const int wn = (wid >> 2) * 64;

    float acc[2][8][4];
#pragma unroll
    for (int mi = 0; mi < 2; mi++)
#pragma unroll
        for (int nb = 0; nb < 8; nb++)
#pragma unroll
            for (int j = 0; j < 4; j++) acc[mi][nb][j] = 0.0f;

    // ldmatrix lane addressing (swizzled row layout: addr = row*128 + (unit ^ (row&7))*16)
    const int prow = wm + (lane & 15);
    const int ak   = lane >> 4;
    const int brow = wn + (lane & 7) + ((lane >> 4) << 3);
    const int bk   = (lane >> 3) & 1;
    const int qr   = lane >> 2;
    const int oc2  = (lane & 3) * 2;

    for (int kk = 0; kk < NITER; kk++) {
        const int s = kk & 1;
        const uint32_t soff = (uint32_t)s * ST_BYTES;
        MBAR_WAIT(mb + s * 8, (kk >> 1) & 1);

#pragma unroll
        for (int kb = 0; kb < 4; kb++) {
            const uint32_t sa = (uint32_t)(((2 * kb + ak) ^ (prow & 7)) << 4);
            const uint32_t sbz = (uint32_t)(((2 * kb + bk) ^ (brow & 7)) << 4);
            uint32_t af[2][4], bf[4][4];
#pragma unroll
            for (int mi = 0; mi < 2; mi++)
                ldsm4(af[mi], sb + soff + (uint32_t)(prow + mi * 16) * 128 + sa);
#pragma unroll
            for (int nj = 0; nj < 4; nj++)
                ldsm4(bf[nj], sb + A_ST + soff + (uint32_t)(brow + nj * 16) * 128 + sbz);
#pragma unroll
            for (int mi = 0; mi < 2; mi++)
#pragma unroll
                for (int nb = 0; nb < 8; nb++) {
                    const uint32_t* bp = bf[nb >> 1];
                    if (nb & 1) mma16816(acc[mi][nb], af[mi], bp[2], bp[3]);
                    else        mma16816(acc[mi][nb], af[mi], bp[0], bp[1]);
                }
        }

        if (kk & 1) {
            // finished xn = xn0 + (kk>>1): store M (fp16), reset acc
            const int xn = xn0 + (kk >> 1);
#pragma unroll
            for (int mi = 0; mi < 2; mi++) {
#pragma unroll
                for (int half = 0; half < 2; half++) {
                    const int row = wm + mi * 16 + half * 8 + qr;
                    __half2* mp = (__half2*)(g_m + ((size_t)xn * NTILE + t0 + row) * 256);
#pragma unroll
                    for (int nb = 0; nb < 8; nb++) {
                        const int oc = wn + nb * 8 + oc2;
                        mp[oc >> 1] = __floats2half2_rn(acc[mi][nb][half * 2 + 0],
                                                        acc[mi][nb][half * 2 + 1]);
                        acc[mi][nb][half * 2 + 0] = 0.0f;
                        acc[mi][nb][half * 2 + 1] = 0.0f;
                    }
                }
            }
        }

        // all warps done reading stage s -> safe to refill it
        __syncthreads();
        if (tid == 0) { FENCE_ASYNC(); issue(kk + 2); }
    }
}

// ---------------- inverse transform kernel ----------------
#define SMB 140                       // bytes per (xn,tj) smem row (70 halfs, odd stride)
#define INV_SMEM (16*28*SMB)          // 62720 B

__global__ __launch_bounds__(512)
void binconv_wino_inverse(const float* __restrict__ bias, float* __restrict__ out) {
    extern __shared__ char sm[];
    const int tid = threadIdx.x;
    const int bi  = blockIdx.x;           // n*28 + ti
    const int n   = bi / 28;
    const int ti  = bi - n * 28;
    const int ocb = blockIdx.y * 64;
    const int tbase = n * TPI + ti * 28;

    for (int u = tid; u < 16 * 28 * 8; u += 512) {
        int xn = u / 224;
        int r  = u - xn * 224;
        int tj = r >> 3;
        int sg = r & 7;
        const uint4 v = *(const uint4*)(g_m + ((size_t)xn * NTILE + tbase + tj) * 256 + ocb + sg * 8);
        char* d = sm + (xn * 28 + tj) * SMB + sg * 16;
        ((uint32_t*)d)[0] = v.x;
        ((uint32_t*)d)[1] = v.y;
        ((uint32_t*)d)[2] = v.z;
        ((uint32_t*)d)[3] = v.w;
    }
    __syncthreads();

    for (int p = tid; p < 28 * 32; p += 512) {
        const int tj  = p % 28;
        const int o2  = p / 28;          // oc pair index
        float m[16][2];
#pragma unroll
        for (int xn = 0; xn < 16; xn++) {
            __half2 hv = *(__half2*)(sm + (xn * 28 + tj) * SMB + o2 * 4);
            m[xn][0] = __low2float(hv);
            m[xn][1] = __high2float(hv);
        }
#pragma unroll
        for (int l = 0; l < 2; l++) {
            float r0[4], r1[4];
#pragma unroll
            for (int nu = 0; nu < 4; nu++) {
                r0[nu] = m[0 * 4 + nu][l] + m[1 * 4 + nu][l] + m[2 * 4 + nu][l];
                r1[nu] = m[1 * 4 + nu][l] - m[2 * 4 + nu][l] - m[3 * 4 + nu][l];
            }
            const int oc = ocb + o2 * 2 + l;
            const float b = __ldg(&bias[oc]);
            float* ob = out + ((size_t)n * CO + oc) * PIXN + (size_t)(2 * ti) * HH + 2 * tj;
            float2 y0 = {r0[0] + r0[1] + r0[2] + b, r0[1] - r0[2] - r0[3] + b};
            float2 y1 = {r1[0] + r1[1] + r1[2] + b, r1[1] - r1[2] - r1[3] + b};
            *(float2*)ob        = y0;
            *(float2*)(ob + HH) = y1;
        }
    }
}

// ---------------- launch ----------------
extern "C" void kernel_launch(void* const* d_in, const int* in_sizes, int n_in,
                              void* d_out, int out_size) {
    const float* x      = (const float*)d_in[0];
    const float* weight = (const float*)d_in[1];
    const float* bias   = (const float*)d_in[2];
    float* out          = (float*)d_out;

    cudaFuncSetAttribute(binconv_wino_gemm,
                         cudaFuncAttributeMaxDynamicSharedMemorySize, SMEM_SZ);
    cudaFuncSetAttribute(binconv_wino_inverse,
                         cudaFuncAttributeMaxDynamicSharedMemorySize, INV_SMEM);

    transform_x_kernel<<<NB * HP, 256>>>(x);
    winograd_x_kernel<<<NTILE * 64 / 256, 256>>>();
    winograd_w_kernel<<<(CO * CI + 255) / 256, 256>>>(weight);

    dim3 ggrid(NBLK, 16 / XNPER);
    binconv_wino_gemm<<<ggrid, 512, SMEM_SZ>>>();

    dim3 igrid(NB * 28, CO / 64);
    binconv_wino_inverse<<<igrid, 512, INV_SMEM>>>(bias, out);
}

// round 15
// speedup vs baseline: 1.5438x; 1.5438x over previous
#include <cuda_runtime.h>
#include <cuda_fp16.h>
#include <cstdint>

// BinaryConv2d via Winograd F(2x2,3x3) + mma.sync HMMA.
// R15: 256-thr CTA, 128x128 tile, 3-stage DMA pipeline, 96 KB -> 2 CTAs/SM (no spill).

#define NB 32
#define CI 128
#define CO 256
#define HH 56
#define HP 58
#define PIXN (HH*HH)
#define TPI  784              // 28*28 tiles per image
#define NTILE (NB*TPI)        // 25088
#define NBLK  196             // NTILE/128
#define XNPER 8
#define NITER (2*XNPER)       // 16 k-chunks per CTA
#define STAGES 3

// padded NHWC fp16
__device__ __half g_xp[(size_t)NB*HP*HP*128];
// Winograd input, chunked+swizzled: [(xn*392 + blk*2 + sub)][pix(128)][64 halfs swz]
__device__ __align__(256) __half g_u2[(size_t)16*NBLK*2*128*64];
// Winograd weights, chunked+swizzled: [(xn*2+sub)][oc(256)][64 halfs swz]
__device__ __align__(256) __half g_v2[(size_t)16*2*256*64];
// GEMM result M[xn][tile][oc]
__device__ __align__(16) __half g_m[(size_t)16*NTILE*CO];

// ---------------- stage 1: pad + fp16 ----------------
__global__ __launch_bounds__(256)
void transform_x_kernel(const float* __restrict__ x) {
    __shared__ float s[128][57];
    const int hp = blockIdx.x % HP;
    const int n  = blockIdx.x / HP;
    const int tid = threadIdx.x;
    const bool interior_h = (hp >= 1 && hp <= HH);

    if (interior_h) {
        const int h = hp - 1;
        const float* src = x + ((size_t)n * CI * HH + h) * HH;
        for (int idx = tid; idx < CI * HH; idx += 256) {
            int c = idx / HH, w = idx - (idx / HH) * HH;
            s[c][w] = src[(size_t)c * PIXN + w];
        }
    }
    __syncthreads();

    const int c  = tid & 127;
    const int wh = tid >> 7;
    __half* ob = g_xp + ((size_t)(n * HP + hp) * HP) * 128 + c;
#pragma unroll 4
    for (int wp = wh * 29; wp < wh * 29 + 29; wp++) {
        float v = 0.0f;
        if (interior_h && wp >= 1 && wp <= HH) v = s[c][wp - 1];
        ob[(size_t)wp * 128] = __float2half_rn(v);
    }
}

// ---------------- stage 2: input Winograd transform (half2, swizzled chunk layout) ----------------
__global__ __launch_bounds__(256)
void winograd_x_kernel() {
    int idx = blockIdx.x * 256 + threadIdx.x;    // over NTILE*64 (channel pairs)
    int c2 = idx & 63;
    int t  = idx >> 6;
    int n  = t / TPI;
    int r  = t - n * TPI;
    int ti = r / 28, tj = r - (r / 28) * 28;

    const __half* base = g_xp + ((size_t)(n * HP + 2 * ti) * HP + 2 * tj) * 128 + 2 * c2;
    float d0[4][4], d1[4][4];
#pragma unroll
    for (int i = 0; i < 4; i++)
#pragma unroll
        for (int s = 0; s < 4; s++) {
            __half2 hv = *(const __half2*)(base + (size_t)(i * HP + s) * 128);
            d0[i][s] = __low2float(hv);
            d1[i][s] = __high2float(hv);
        }

    float t0[4][4], t1[4][4];
#pragma unroll
    for (int s = 0; s < 4; s++) {
        t0[0][s] = d0[0][s] - d0[2][s];  t1[0][s] = d1[0][s] - d1[2][s];
        t0[1][s] = d0[1][s] + d0[2][s];  t1[1][s] = d1[1][s] + d1[2][s];
        t0[2][s] = d0[2][s] - d0[1][s];  t1[2][s] = d1[2][s] - d1[1][s];
        t0[3][s] = d0[1][s] - d0[3][s];  t1[3][s] = d1[1][s] - d1[3][s];
    }
    float u0[4][4], u1[4][4];
#pragma unroll
    for (int i = 0; i < 4; i++) {
        u0[i][0] = t0[i][0] - t0[i][2];  u1[i][0] = t1[i][0] - t1[i][2];
        u0[i][1] = t0[i][1] + t0[i][2];  u1[i][1] = t1[i][1] + t1[i][2];
        u0[i][2] = t0[i][2] - t0[i][1];  u1[i][2] = t1[i][2] - t1[i][1];
        u0[i][3] = t0[i][1] - t0[i][3];  u1[i][3] = t1[i][1] - t1[i][3];
    }

    const int blk = t >> 7;
    const int pix = t & 127;
    const int c   = 2 * c2;
    const int sub = c >> 6;
    const int e   = c & 7;                          // even
    const int uw  = ((c >> 3) & 7) ^ (pix & 7);     // swizzled 16B unit
    const size_t inner = ((size_t)pix * 64) + uw * 8 + e;
#pragma unroll
    for (int xi = 0; xi < 4; xi++)
#pragma unroll
        for (int nu = 0; nu < 4; nu++) {
            int xn = xi * 4 + nu;
            *(__half2*)&g_u2[((size_t)xn * (NBLK * 2) + blk * 2 + sub) * 8192 + inner] =
                __floats2half2_rn(u0[xi][nu], u1[xi][nu]);
        }
}

// ---------------- stage 3: weight Winograd transform (swizzled chunk layout) ----------------
__global__ __launch_bounds__(256)
void winograd_w_kernel(const float* __restrict__ w) {
    int idx = blockIdx.x * 256 + threadIdx.x;    // over CO*CI
    if (idx >= CO * CI) return;
    int oc = idx >> 7;
    int c  = idx & 127;
    float g[3][3];
#pragma unroll
    for (int r = 0; r < 3; r++)
#pragma unroll
        for (int s = 0; s < 3; s++)
            g[r][s] = (w[((size_t)(oc * CI + c)) * 9 + r * 3 + s] >= 0.0f) ? 1.0f : -1.0f;
    float gg[4][3];
#pragma unroll
    for (int s = 0; s < 3; s++) {
        gg[0][s] = g[0][s];
        gg[1][s] = 0.5f * (g[0][s] + g[1][s] + g[2][s]);
        gg[2][s] = 0.5f * (g[0][s] - g[1][s] + g[2][s]);
        gg[3][s] = g[2][s];
    }
    const int sub = c >> 6;
    const int e   = c & 7;
    const int uw  = ((c >> 3) & 7) ^ (oc & 7);
    const size_t inner = ((size_t)oc * 64) + uw * 8 + e;
#pragma unroll
    for (int i = 0; i < 4; i++) {
        float v[4];
        v[0] = gg[i][0];
        v[1] = 0.5f * (gg[i][0] + gg[i][1] + gg[i][2]);
        v[2] = 0.5f * (gg[i][0] - gg[i][1] + gg[i][2]);
        v[3] = gg[i][2];
#pragma unroll
        for (int nu = 0; nu < 4; nu++) {
            int xn = i * 4 + nu;
            g_v2[((size_t)xn * 2 + sub) * 16384 + inner] = __float2half_rn(v[nu]);
        }
    }
}

// ---------------- GEMM kernel ----------------
__device__ __forceinline__ uint32_t smem_u32(const void* p) {
    uint32_t a;
    asm("{ .reg .u64 t; cvta.to.shared.u64 t, %1; cvt.u32.u64 %0, t; }" : "=r"(a) : "l"(p));
    return a;
}
__device__ __forceinline__ void bulk_cp(uint32_t dst, const void* src, uint32_t bytes, uint32_t mbar) {
    asm volatile("cp.async.bulk.shared::cta.global.mbarrier::complete_tx::bytes [%0], [%1], %2, [%3];"
        :: "r"(dst), "l"(src), "r"(bytes), "r"(mbar) : "memory");
}
#define MBAR_INIT(a, c) asm volatile("mbarrier.init.shared.b64 [%0], %1;" :: "r"(a), "r"(c) : "memory")
#define MBAR_EXPECT(a, b) asm volatile("mbarrier.arrive.expect_tx.shared.b64 _, [%0], %1;" :: "r"(a), "r"(b) : "memory")
#define FENCE_ASYNC() asm volatile("fence.proxy.async.shared::cta;" ::: "memory")
#define MBAR_WAIT(a, ph) do { \
    uint32_t _m = (a); uint32_t _p = (ph); uint32_t _d; \
    asm volatile("{\n\t.reg .pred p;\n\tmbarrier.try_wait.parity.acquire.cta.shared::cta.b64 p, [%1], %2;\n\tselp.b32 %0,1,0,p;\n\t}" \
        : "=r"(_d) : "r"(_m), "r"(_p) : "memory"); \
    if (!_d) { \
        asm volatile("{\n\t.reg .pred P1;\nWL_%=:\n\tmbarrier.try_wait.parity.acquire.cta.shared::cta.b64 P1, [%0], %1, 0x989680;\n\t@P1 bra.uni WD_%=;\n\tbra.uni WL_%=;\nWD_%=:\n\t}" \
            :: "r"(_m), "r"(_p) : "memory"); \
    } } while (0)

__device__ __forceinline__ void ldsm4(uint32_t* r, uint32_t addr) {
    asm volatile("ldmatrix.sync.aligned.m8n8.x4.shared.b16 {%0,%1,%2,%3}, [%4];"
        : "=r"(r[0]), "=r"(r[1]), "=r"(r[2]), "=r"(r[3]) : "r"(addr));
}
__device__ __forceinline__ void mma16816(float* c, const uint32_t* a, uint32_t b0, uint32_t b1) {
    asm volatile("mma.sync.aligned.m16n8k16.row.col.f32.f16.f16.f32 "
        "{%0,%1,%2,%3}, {%4,%5,%6,%7}, {%8,%9}, {%0,%1,%2,%3};"
        : "+f"(c[0]), "+f"(c[1]), "+f"(c[2]), "+f"(c[3])
        : "r"(a[0]), "r"(a[1]), "r"(a[2]), "r"(a[3]), "r"(b0), "r"(b1));
}

#define A_ST  16384                  // 128 pix x 64 k x fp16 (swizzled rows)
#define B_ST  16384                  // 128 oc  x 64 k x fp16 (swizzled rows)
#define ST_BYTES (A_ST + B_ST)       // 32 KB / stage
#define SMEM_SZ (STAGES * ST_BYTES)  // 96 KB -> 2 CTAs/SM

__global__ __launch_bounds__(256, 2)
void binconv_wino_gemm(void) {
    extern __shared__ char smem[];
    __shared__ __align__(8) uint64_t mbar[STAGES];
    const uint32_t sb = smem_u32(smem);
    const uint32_t mb = smem_u32(&mbar[0]);

    const int tid  = threadIdx.x;
    const int wid  = tid >> 5;
    const int lane = tid & 31;
    const int blk  = blockIdx.x;
    const int t0   = blk * 128;
    const int ocb  = blockIdx.y * 128;       // oc half
    const int xn0  = blockIdx.z * XNPER;

    if (tid == 0) {
#pragma unroll
        for (int s = 0; s < STAGES; s++) MBAR_INIT(mb + s * 8, 1);
    }
    __syncthreads();

    auto issue = [&](int kk) {
        if (kk < NITER) {
            const int s   = kk % STAGES;
            const int xl  = kk >> 1;
            const int sub = kk & 1;
            const uint32_t soff = (uint32_t)s * ST_BYTES;
            MBAR_EXPECT(mb + s * 8, (uint32_t)ST_BYTES);
            bulk_cp(sb + soff,
                    g_u2 + ((size_t)(xn0 + xl) * (NBLK * 2) + blk * 2 + sub) * 8192,
                    A_ST, mb + s * 8);
            bulk_cp(sb + A_ST + soff,
                    g_v2 + ((size_t)(xn0 + xl) * 2 + sub) * 16384 + (size_t)ocb * 64,
                    B_ST, mb + s * 8);
        }
    };

    if (tid == 0) { FENCE_ASYNC(); issue(0); issue(1); }

    // warp tiling: 4 (M) x 2 (N); warp tile 32 x 64
    const int wm = (wid & 3) * 32;
    const int wn = (wid >> 2) * 64;

    float acc[2][8][4];
#pragma unroll
    for (int mi = 0; mi < 2; mi++)
#pragma unroll
        for (int nb = 0; nb < 8; nb++)
#pragma unroll
            for (int j = 0; j < 4; j++) acc[mi][nb][j] = 0.0f;

    // ldmatrix lane addressing (swizzled row layout: addr = row*128 + (unit ^ (row&7))*16)
    const int prow = wm + (lane & 15);
    const int ak   = lane >> 4;
    const int brow = wn + (lane & 7) + ((lane >> 4) << 3);
    const int bk   = (lane >> 3) & 1;
    const int qr   = lane >> 2;
    const int oc2  = (lane & 3) * 2;

    for (int kk = 0; kk < NITER; kk++) {
        const int s = kk % STAGES;
        const uint32_t soff = (uint32_t)s * ST_BYTES;
        MBAR_WAIT(mb + s * 8, (kk / STAGES) & 1);
        __syncthreads();
        if (tid == 0) { FENCE_ASYNC(); issue(kk + 2); }

#pragma unroll
        for (int kb = 0; kb < 4; kb++) {
            const uint32_t sa = (uint32_t)(((2 * kb + ak) ^ (prow & 7)) << 4);
            const uint32_t sbz = (uint32_t)(((2 * kb + bk) ^ (brow & 7)) << 4);
            uint32_t af[2][4], bf[4][4];
#pragma unroll
            for (int mi = 0; mi < 2; mi++)
                ldsm4(af[mi], sb + soff + (uint32_t)(prow + mi * 16) * 128 + sa);
#pragma unroll
            for (int nj = 0; nj < 4; nj++)
                ldsm4(bf[nj], sb + A_ST + soff + (uint32_t)(brow + nj * 16) * 128 + sbz);
#pragma unroll
            for (int mi = 0; mi < 2; mi++)
#pragma unroll
                for (int nb = 0; nb < 8; nb++) {
                    const uint32_t* bp = bf[nb >> 1];
                    if (nb & 1) mma16816(acc[mi][nb], af[mi], bp[2], bp[3]);
                    else        mma16816(acc[mi][nb], af[mi], bp[0], bp[1]);
                }
        }

        if (kk & 1) {
            // finished xn = xn0 + (kk>>1): store M (fp16), reset acc
            const int xn = xn0 + (kk >> 1);
#pragma unroll
            for (int mi = 0; mi < 2; mi++) {
#pragma unroll
                for (int half = 0; half < 2; half++) {
                    const int row = wm + mi * 16 + half * 8 + qr;
                    __half2* mp = (__half2*)(g_m + ((size_t)xn * NTILE + t0 + row) * 256 + ocb);
#pragma unroll
                    for (int nb = 0; nb < 8; nb++) {
                        const int ocl = wn + nb * 8 + oc2;
                        mp[ocl >> 1] = __floats2half2_rn(acc[mi][nb][half * 2 + 0],
                                                         acc[mi][nb][half * 2 + 1]);
                        acc[mi][nb][half * 2 + 0] = 0.0f;
                        acc[mi][nb][half * 2 + 1] = 0.0f;
                    }
                }
            }
        }
    }
}

// ---------------- inverse transform kernel ----------------
#define SMB 140                       // bytes per (xn,tj) smem row (70 halfs, odd stride)
#define INV_SMEM (16*28*SMB)          // 62720 B

__global__ __launch_bounds__(512)
void binconv_wino_inverse(const float* __restrict__ bias, float* __restrict__ out) {
    extern __shared__ char sm[];
    const int tid = threadIdx.x;
    const int bi  = blockIdx.x;           // n*28 + ti
    const int n   = bi / 28;
    const int ti  = bi - n * 28;
    const int ocb = blockIdx.y * 64;
    const int tbase = n * TPI + ti * 28;

    for (int u = tid; u < 16 * 28 * 8; u += 512) {
        int xn = u / 224;
        int r  = u - xn * 224;
        int tj = r >> 3;
        int sg = r & 7;
        const uint4 v = *(const uint4*)(g_m + ((size_t)xn * NTILE + tbase + tj) * 256 + ocb + sg * 8);
        char* d = sm + (xn * 28 + tj) * SMB + sg * 16;
        ((uint32_t*)d)[0] = v.x;
        ((uint32_t*)d)[1] = v.y;
        ((uint32_t*)d)[2] = v.z;
        ((uint32_t*)d)[3] = v.w;
    }
    __syncthreads();

    for (int p = tid; p < 28 * 32; p += 512) {
        const int tj  = p % 28;
        const int o2  = p / 28;          // oc pair index
        float m[16][2];
#pragma unroll
        for (int xn = 0; xn < 16; xn++) {
            __half2 hv = *(__half2*)(sm + (xn * 28 + tj) * SMB + o2 * 4);
            m[xn][0] = __low2float(hv);
            m[xn][1] = __high2float(hv);
        }
#pragma unroll
        for (int l = 0; l < 2; l++) {
            float r0[4], r1[4];
#pragma unroll
            for (int nu = 0; nu < 4; nu++) {
                r0[nu] = m[0 * 4 + nu][l] + m[1 * 4 + nu][l] + m[2 * 4 + nu][l];
                r1[nu] = m[1 * 4 + nu][l] - m[2 * 4 + nu][l] - m[3 * 4 + nu][l];
            }
            const int oc = ocb + o2 * 2 + l;
            const float b = __ldg(&bias[oc]);
            float* ob = out + ((size_t)n * CO + oc) * PIXN + (size_t)(2 * ti) * HH + 2 * tj;
            float2 y0 = {r0[0] + r0[1] + r0[2] + b, r0[1] - r0[2] - r0[3] + b};
            float2 y1 = {r1[0] + r1[1] + r1[2] + b, r1[1] - r1[2] - r1[3] + b};
            *(float2*)ob        = y0;
            *(float2*)(ob + HH) = y1;
        }
    }
}

// ---------------- launch ----------------
extern "C" void kernel_launch(void* const* d_in, const int* in_sizes, int n_in,
                              void* d_out, int out_size) {
    const float* x      = (const float*)d_in[0];
    const float* weight = (const float*)d_in[1];
    const float* bias   = (const float*)d_in[2];
    float* out          = (float*)d_out;

    cudaFuncSetAttribute(binconv_wino_gemm,
                         cudaFuncAttributeMaxDynamicSharedMemorySize, SMEM_SZ);
    cudaFuncSetAttribute(binconv_wino_inverse,
                         cudaFuncAttributeMaxDynamicSharedMemorySize, INV_SMEM);

    transform_x_kernel<<<NB * HP, 256>>>(x);
    winograd_x_kernel<<<NTILE * 64 / 256, 256>>>();
    winograd_w_kernel<<<(CO * CI + 255) / 256, 256>>>(weight);

    dim3 ggrid(NBLK, 2, 16 / XNPER);
    binconv_wino_gemm<<<ggrid, 256, SMEM_SZ>>>();

    dim3 igrid(NB * 28, CO / 64);
    binconv_wino_inverse<<<igrid, 512, INV_SMEM>>>(bias, out);
}

// round 16
// speedup vs baseline: 2.0992x; 1.3597x over previous
#include <cuda_runtime.h>
#include <cuda_fp16.h>
#include <cstdint>

// BinaryConv2d via Winograd F(2x2,3x3) + mma.sync HMMA.
// R16: R13 pipeline (4-stage bulk-DMA, XNPER=8) + 64x64 warp tiles (256 thr, 8 warps)
//      -> halves LDSM fragment traffic per HMMA.

#define NB 32
#define CI 128
#define CO 256
#define HH 56
#define HP 58
#define PIXN (HH*HH)
#define TPI  784              // 28*28 tiles per image
#define NTILE (NB*TPI)        // 25088
#define NBLK  196             // NTILE/128
#define XNPER 8
#define NITER (2*XNPER)       // 16 k-chunks per CTA
#define STAGES 4

// padded NHWC fp16
__device__ __half g_xp[(size_t)NB*HP*HP*128];
// Winograd input, chunked+swizzled: [(xn*392 + blk*2 + sub)][pix(128)][64 halfs swz]
__device__ __align__(256) __half g_u2[(size_t)16*NBLK*2*128*64];
// Winograd weights, chunked+swizzled: [(xn*2+sub)][oc(256)][64 halfs swz]
__device__ __align__(256) __half g_v2[(size_t)16*2*256*64];
// GEMM result M[xn][tile][oc]
__device__ __align__(16) __half g_m[(size_t)16*NTILE*CO];

// ---------------- stage 1: pad + fp16 ----------------
__global__ __launch_bounds__(256)
void transform_x_kernel(const float* __restrict__ x) {
    __shared__ float s[128][57];
    const int hp = blockIdx.x % HP;
    const int n  = blockIdx.x / HP;
    const int tid = threadIdx.x;
    const bool interior_h = (hp >= 1 && hp <= HH);

    if (interior_h) {
        const int h = hp - 1;
        const float* src = x + ((size_t)n * CI * HH + h) * HH;
        for (int idx = tid; idx < CI * HH; idx += 256) {
            int c = idx / HH, w = idx - (idx / HH) * HH;
            s[c][w] = src[(size_t)c * PIXN + w];
        }
    }
    __syncthreads();

    const int c  = tid & 127;
    const int wh = tid >> 7;
    __half* ob = g_xp + ((size_t)(n * HP + hp) * HP) * 128 + c;
#pragma unroll 4
    for (int wp = wh * 29; wp < wh * 29 + 29; wp++) {
        float v = 0.0f;
        if (interior_h && wp >= 1 && wp <= HH) v = s[c][wp - 1];
        ob[(size_t)wp * 128] = __float2half_rn(v);
    }
}

// ---------------- stage 2: input Winograd transform (half2, swizzled chunk layout) ----------------
__global__ __launch_bounds__(256)
void winograd_x_kernel() {
    int idx = blockIdx.x * 256 + threadIdx.x;    // over NTILE*64 (channel pairs)
    int c2 = idx & 63;
    int t  = idx >> 6;
    int n  = t / TPI;
    int r  = t - n * TPI;
    int ti = r / 28, tj = r - (r / 28) * 28;

    const __half* base = g_xp + ((size_t)(n * HP + 2 * ti) * HP + 2 * tj) * 128 + 2 * c2;
    float d0[4][4], d1[4][4];
#pragma unroll
    for (int i = 0; i < 4; i++)
#pragma unroll
        for (int s = 0; s < 4; s++) {
            __half2 hv = *(const __half2*)(base + (size_t)(i * HP + s) * 128);
            d0[i][s] = __low2float(hv);
            d1[i][s] = __high2float(hv);
        }

    float t0[4][4], t1[4][4];
#pragma unroll
    for (int s = 0; s < 4; s++) {
        t0[0][s] = d0[0][s] - d0[2][s];  t1[0][s] = d1[0][s] - d1[2][s];
        t0[1][s] = d0[1][s] + d0[2][s];  t1[1][s] = d1[1][s] + d1[2][s];
        t0[2][s] = d0[2][s] - d0[1][s];  t1[2][s] = d1[2][s] - d1[1][s];
        t0[3][s] = d0[1][s] - d0[3][s];  t1[3][s] = d1[1][s] - d1[3][s];
    }
    float u0[4][4], u1[4][4];
#pragma unroll
    for (int i = 0; i < 4; i++) {
        u0[i][0] = t0[i][0] - t0[i][2];  u1[i][0] = t1[i][0] - t1[i][2];
        u0[i][1] = t0[i][1] + t0[i][2];  u1[i][1] = t1[i][1] + t1[i][2];
        u0[i][2] = t0[i][2] - t0[i][1];  u1[i][2] = t1[i][2] - t1[i][1];
        u0[i][3] = t0[i][1] - t0[i][3];  u1[i][3] = t1[i][1] - t1[i][3];
    }

    const int blk = t >> 7;
    const int pix = t & 127;
    const int c   = 2 * c2;
    const int sub = c >> 6;
    const int e   = c & 7;                          // even
    const int uw  = ((c >> 3) & 7) ^ (pix & 7);     // swizzled 16B unit
    const size_t inner = ((size_t)pix * 64) + uw * 8 + e;
#pragma unroll
    for (int xi = 0; xi < 4; xi++)
#pragma unroll
        for (int nu = 0; nu < 4; nu++) {
            int xn = xi * 4 + nu;
            *(__half2*)&g_u2[((size_t)xn * (NBLK * 2) + blk * 2 + sub) * 8192 + inner] =
                __floats2half2_rn(u0[xi][nu], u1[xi][nu]);
        }
}

// ---------------- stage 3: weight Winograd transform (swizzled chunk layout) ----------------
__global__ __launch_bounds__(256)
void winograd_w_kernel(const float* __restrict__ w) {
    int idx = blockIdx.x * 256 + threadIdx.x;    // over CO*CI
    if (idx >= CO * CI) return;
    int oc = idx >> 7;
    int c  = idx & 127;
    float g[3][3];
#pragma unroll
    for (int r = 0; r < 3; r++)
#pragma unroll
        for (int s = 0; s < 3; s++)
            g[r][s] = (w[((size_t)(oc * CI + c)) * 9 + r * 3 + s] >= 0.0f) ? 1.0f : -1.0f;
    float gg[4][3];
#pragma unroll
    for (int s = 0; s < 3; s++) {
        gg[0][s] = g[0][s];
        gg[1][s] = 0.5f * (g[0][s] + g[1][s] + g[2][s]);
        gg[2][s] = 0.5f * (g[0][s] - g[1][s] + g[2][s]);
        gg[3][s] = g[2][s];
    }
    const int sub = c >> 6;
    const int e   = c & 7;
    const int uw  = ((c >> 3) & 7) ^ (oc & 7);
    const size_t inner = ((size_t)oc * 64) + uw * 8 + e;
#pragma unroll
    for (int i = 0; i < 4; i++) {
        float v[4];
        v[0] = gg[i][0];
        v[1] = 0.5f * (gg[i][0] + gg[i][1] + gg[i][2]);
        v[2] = 0.5f * (gg[i][0] - gg[i][1] + gg[i][2]);
        v[3] = gg[i][2];
#pragma unroll
        for (int nu = 0; nu < 4; nu++) {
            int xn = i * 4 + nu;
            g_v2[((size_t)xn * 2 + sub) * 16384 + inner] = __float2half_rn(v[nu]);
        }
    }
}

// ---------------- GEMM kernel ----------------
__device__ __forceinline__ uint32_t smem_u32(const void* p) {
    uint32_t a;
    asm("{ .reg .u64 t; cvta.to.shared.u64 t, %1; cvt.u32.u64 %0, t; }" : "=r"(a) : "l"(p));
    return a;
}
__device__ __forceinline__ void bulk_cp(uint32_t dst, const void* src, uint32_t bytes, uint32_t mbar) {
    asm volatile("cp.async.bulk.shared::cta.global.mbarrier::complete_tx::bytes [%0], [%1], %2, [%3];"
        :: "r"(dst), "l"(src), "r"(bytes), "r"(mbar) : "memory");
}
#define MBAR_INIT(a, c) asm volatile("mbarrier.init.shared.b64 [%0], %1;" :: "r"(a), "r"(c) : "memory")
#define MBAR_EXPECT(a, b) asm volatile("mbarrier.arrive.expect_tx.shared.b64 _, [%0], %1;" :: "r"(a), "r"(b) : "memory")
#define FENCE_ASYNC() asm volatile("fence.proxy.async.shared::cta;" ::: "memory")
#define MBAR_WAIT(a, ph) do { \
    uint32_t _m = (a); uint32_t _p = (ph); uint32_t _d; \
    asm volatile("{\n\t.reg .pred p;\n\tmbarrier.try_wait.parity.acquire.cta.shared::cta.b64 p, [%1], %2;\n\tselp.b32 %0,1,0,p;\n\t}" \
        : "=r"(_d) : "r"(_m), "r"(_p) : "memory"); \
    if (!_d) { \
        asm volatile("{\n\t.reg .pred P1;\nWL_%=:\n\tmbarrier.try_wait.parity.acquire.cta.shared::cta.b64 P1, [%0], %1, 0x989680;\n\t@P1 bra.uni WD_%=;\n\tbra.uni WL_%=;\nWD_%=:\n\t}" \
            :: "r"(_m), "r"(_p) : "memory"); \
    } } while (0)

__device__ __forceinline__ void ldsm4(uint32_t* r, uint32_t addr) {
    asm volatile("ldmatrix.sync.aligned.m8n8.x4.shared.b16 {%0,%1,%2,%3}, [%4];"
        : "=r"(r[0]), "=r"(r[1]), "=r"(r[2]), "=r"(r[3]) : "r"(addr));
}
__device__ __forceinline__ void mma16816(float* c, const uint32_t* a, uint32_t b0, uint32_t b1) {
    asm volatile("mma.sync.aligned.m16n8k16.row.col.f32.f16.f16.f32 "
        "{%0,%1,%2,%3}, {%4,%5,%6,%7}, {%8,%9}, {%0,%1,%2,%3};"
        : "+f"(c[0]), "+f"(c[1]), "+f"(c[2]), "+f"(c[3])
        : "r"(a[0]), "r"(a[1]), "r"(a[2]), "r"(a[3]), "r"(b0), "r"(b1));
}

#define A_ST  16384                  // 128 pix x 64 k x fp16 (swizzled rows)
#define B_ST  32768                  // 256 oc  x 64 k x fp16 (swizzled rows)
#define ST_BYTES (A_ST + B_ST)       // 48 KB / stage
#define SMEM_SZ (STAGES * ST_BYTES)  // 192 KB

__global__ __launch_bounds__(256, 1)
void binconv_wino_gemm(void) {
    extern __shared__ char smem[];
    __shared__ __align__(8) uint64_t mbar[STAGES];
    const uint32_t sb = smem_u32(smem);
    const uint32_t mb = smem_u32(&mbar[0]);

    const int tid  = threadIdx.x;
    const int wid  = tid >> 5;
    const int lane = tid & 31;
    const int blk  = blockIdx.x;
    const int t0   = blk * 128;
    const int xn0  = blockIdx.y * XNPER;

    if (tid == 0) {
#pragma unroll
        for (int s = 0; s < STAGES; s++) MBAR_INIT(mb + s * 8, 1);
    }
    __syncthreads();

    auto issue = [&](int kk) {
        if (kk < NITER) {
            const int s   = kk % STAGES;
            const int xl  = kk >> 1;
            const int sub = kk & 1;
            const uint32_t soff = (uint32_t)s * ST_BYTES;
            MBAR_EXPECT(mb + s * 8, (uint32_t)ST_BYTES);
            bulk_cp(sb + soff,
                    g_u2 + ((size_t)(xn0 + xl) * (NBLK * 2) + blk * 2 + sub) * 8192,
                    A_ST, mb + s * 8);
            bulk_cp(sb + A_ST + soff,
                    g_v2 + ((size_t)(xn0 + xl) * 2 + sub) * 16384,
                    B_ST, mb + s * 8);
        }
    };

    if (tid == 0) { FENCE_ASYNC(); issue(0); issue(1); issue(2); }

    // warp tiling: 2 (M) x 4 (N); warp tile 64 x 64
    const int wm = (wid & 1) * 64;
    const int wn = (wid >> 1) * 64;

    float acc[4][8][4];
#pragma unroll
    for (int mi = 0; mi < 4; mi++)
#pragma unroll
        for (int nb = 0; nb < 8; nb++)
#pragma unroll
            for (int j = 0; j < 4; j++) acc[mi][nb][j] = 0.0f;

    // ldmatrix lane addressing (swizzled row layout: addr = row*128 + (unit ^ (row&7))*16)
    const int prow = wm + (lane & 15);
    const int ak   = lane >> 4;
    const int brow = wn + (lane & 7) + ((lane >> 4) << 3);
    const int bk   = (lane >> 3) & 1;
    const int qr   = lane >> 2;
    const int oc2  = (lane & 3) * 2;

    for (int kk = 0; kk < NITER; kk++) {
        const int s = kk % STAGES;
        const uint32_t soff = (uint32_t)s * ST_BYTES;
        MBAR_WAIT(mb + s * 8, (kk / STAGES) & 1);
        __syncthreads();
        if (tid == 0) { FENCE_ASYNC(); issue(kk + 3); }

#pragma unroll
        for (int kb = 0; kb < 4; kb++) {
            const uint32_t sa = (uint32_t)(((2 * kb + ak) ^ (prow & 7)) << 4);
            const uint32_t sbz = (uint32_t)(((2 * kb + bk) ^ (brow & 7)) << 4);
            uint32_t af[4][4], bf[4][4];
#pragma unroll
            for (int mi = 0; mi < 4; mi++)
                ldsm4(af[mi], sb + soff + (uint32_t)(prow + mi * 16) * 128 + sa);
#pragma unroll
            for (int nj = 0; nj < 4; nj++)
                ldsm4(bf[nj], sb + A_ST + soff + (uint32_t)(brow + nj * 16) * 128 + sbz);
#pragma unroll
            for (int mi = 0; mi < 4; mi++)
#pragma unroll
                for (int nb = 0; nb < 8; nb++) {
                    const uint32_t* bp = bf[nb >> 1];
                    if (nb & 1) mma16816(acc[mi][nb], af[mi], bp[2], bp[3]);
                    else        mma16816(acc[mi][nb], af[mi], bp[0], bp[1]);
                }
        }

        if (kk & 1) {
            // finished xn = xn0 + (kk>>1): store M (fp16), reset acc
            const int xn = xn0 + (kk >> 1);
#pragma unroll
            for (int mi = 0; mi < 4; mi++) {
#pragma unroll
                for (int half = 0; half < 2; half++) {
                    const int row = wm + mi * 16 + half * 8 + qr;
                    __half2* mp = (__half2*)(g_m + ((size_t)xn * NTILE + t0 + row) * 256);
#pragma unroll
                    for (int nb = 0; nb < 8; nb++) {
                        const int oc = wn + nb * 8 + oc2;
                        mp[oc >> 1] = __floats2half2_rn(acc[mi][nb][half * 2 + 0],
                                                        acc[mi][nb][half * 2 + 1]);
                        acc[mi][nb][half * 2 + 0] = 0.0f;
                        acc[mi][nb][half * 2 + 1] = 0.0f;
                    }
                }
            }
        }
    }
}

// ---------------- inverse transform kernel ----------------
#define SMB 140                       // bytes per (xn,tj) smem row (70 halfs, odd stride)
#define INV_SMEM (16*28*SMB)          // 62720 B

__global__ __launch_bounds__(512)
void binconv_wino_inverse(const float* __restrict__ bias, float* __restrict__ out) {
    extern __shared__ char sm[];
    const int tid = threadIdx.x;
    const int bi  = blockIdx.x;           // n*28 + ti
    const int n   = bi / 28;
    const int ti  = bi - n * 28;
    const int ocb = blockIdx.y * 64;
    const int tbase = n * TPI + ti * 28;

    for (int u = tid; u < 16 * 28 * 8; u += 512) {
        int xn = u / 224;
        int r  = u - xn * 224;
        int tj = r >> 3;
        int sg = r & 7;
        const uint4 v = *(const uint4*)(g_m + ((size_t)xn * NTILE + tbase + tj) * 256 + ocb + sg * 8);
        char* d = sm + (xn * 28 + tj) * SMB + sg * 16;
        ((uint32_t*)d)[0] = v.x;
        ((uint32_t*)d)[1] = v.y;
        ((uint32_t*)d)[2] = v.z;
        ((uint32_t*)d)[3] = v.w;
    }
    __syncthreads();

    for (int p = tid; p < 28 * 32; p += 512) {
        const int tj  = p % 28;
        const int o2  = p / 28;          // oc pair index
        float m[16][2];
#pragma unroll
        for (int xn = 0; xn < 16; xn++) {
            __half2 hv = *(__half2*)(sm + (xn * 28 + tj) * SMB + o2 * 4);
            m[xn][0] = __low2float(hv);
            m[xn][1] = __high2float(hv);
        }
#pragma unroll
        for (int l = 0; l < 2; l++) {
            float r0[4], r1[4];
#pragma unroll
            for (int nu = 0; nu < 4; nu++) {
                r0[nu] = m[0 * 4 + nu][l] + m[1 * 4 + nu][l] + m[2 * 4 + nu][l];
                r1[nu] = m[1 * 4 + nu][l] - m[2 * 4 + nu][l] - m[3 * 4 + nu][l];
            }
            const int oc = ocb + o2 * 2 + l;
            const float b = __ldg(&bias[oc]);
            float* ob = out + ((size_t)n * CO + oc) * PIXN + (size_t)(2 * ti) * HH + 2 * tj;
            float2 y0 = {r0[0] + r0[1] + r0[2] + b, r0[1] - r0[2] - r0[3] + b};
            float2 y1 = {r1[0] + r1[1] + r1[2] + b, r1[1] - r1[2] - r1[3] + b};
            *(float2*)ob        = y0;
            *(float2*)(ob + HH) = y1;
        }
    }
}

// ---------------- launch ----------------
extern "C" void kernel_launch(void* const* d_in, const int* in_sizes, int n_in,
                              void* d_out, int out_size) {
    const float* x      = (const float*)d_in[0];
    const float* weight = (const float*)d_in[1];
    const float* bias   = (const float*)d_in[2];
    float* out          = (float*)d_out;

    cudaFuncSetAttribute(binconv_wino_gemm,
                         cudaFuncAttributeMaxDynamicSharedMemorySize, SMEM_SZ);
    cudaFuncSetAttribute(binconv_wino_inverse,
                         cudaFuncAttributeMaxDynamicSharedMemorySize, INV_SMEM);

    transform_x_kernel<<<NB * HP, 256>>>(x);
    winograd_x_kernel<<<NTILE * 64 / 256, 256>>>();
    winograd_w_kernel<<<(CO * CI + 255) / 256, 256>>>(weight);

    dim3 ggrid(NBLK, 16 / XNPER);
    binconv_wino_gemm<<<ggrid, 256, SMEM_SZ>>>();

    dim3 igrid(NB * 28, CO / 64);
    binconv_wino_inverse<<<igrid, 512, INV_SMEM>>>(bias, out);
}